// round 13
// baseline (speedup 1.0000x reference)
#include <cuda_runtime.h>
#include <cuda_fp16.h>
#include <cstdint>

// Problem constants (fixed by the dataset)
#define N_NODES 50000
#define NPAD    50048            // 391 * 128
#define N_EDGES 800000
#define D       128
#define NGRAPH  256
#define OUTF    256
#define N_TILES (NPAD / 128)     // 391  (pool tiling)
#define MLP_TILES (NPAD / 64)    // 782  (MLP M=64 tiling)
#define CAP     64               // max in-degree capacity (Poisson(16) tail ~1e-13)

// ---------------- device scratch (no allocations allowed) ----------------
__device__ float    g_hA[(size_t)NPAD * D];
__device__ float    g_hB[(size_t)NPAD * D];
__device__ unsigned g_zh[(size_t)NPAD * 64];   // z hi, packed half2, [node][64 u32]
__device__ unsigned g_zl[(size_t)NPAD * 64];   // z lo
__device__ __half   g_wh[6 * 2 * 128 * 64];    // W hi, [mat][khalf][n][64 halves]
__device__ __half   g_wl[6 * 2 * 128 * 64];    // W lo
__device__ int      g_counts[N_NODES];
__device__ int      g_bkt[(size_t)N_NODES * CAP];
__device__ float    g_gsum[NGRAPH * D];
__device__ unsigned g_gmax[NGRAPH * D];
__device__ int      g_gcnt[NGRAPH];

__device__ __forceinline__ void fsplit(float v, __half& hi, __half& lo) {
    hi = __float2half_rn(v);
    lo = __float2half_rn(v - __half2float(hi));
}
__device__ __forceinline__ unsigned pack2(__half a, __half b) {
    union { __half2 h; unsigned u; } q;
    q.h = __halves2half2(a, b);
    return q.u;
}

// ---------------- init + one-time W split (launch #1) ----------------
__global__ void zero_kernel(const float* __restrict__ w1_0,
                            const float* __restrict__ w2_0,
                            const float* __restrict__ gw1,
                            const float* __restrict__ gw2) {
    int i = blockIdx.x * blockDim.x + threadIdx.x;
    if (i < N_NODES) g_counts[i] = 0;
    if (i < NGRAPH * D) { g_gsum[i] = 0.f; g_gmax[i] = 0u; }
    if (i < NGRAPH) g_gcnt[i] = 0;
    if (i < 6 * 128 * 32) {
        int m = i / (128 * 32);
        int r = i % (128 * 32);
        int k = r >> 5;                  // 0..127
        int n4 = (r & 31) * 4;
        const float* W;
        switch (m) {
            case 0: W = w1_0; break;
            case 1: W = w2_0; break;
            case 2: W = gw1; break;
            case 3: W = gw2; break;
            case 4: W = gw1 + 128 * 128; break;
            default: W = gw2 + 128 * 128; break;
        }
        float4 v = ((const float4*)W)[k * 32 + (r & 31)];
        int half = k >> 6, kl = k & 63;
        size_t base = ((size_t)(m * 2 + half) * 128 + n4) * 64 + kl;
        __half h, l;
        fsplit(v.x, h, l); g_wh[base]          = h; g_wl[base]          = l;
        fsplit(v.y, h, l); g_wh[base + 64]     = h; g_wl[base + 64]     = l;
        fsplit(v.z, h, l); g_wh[base + 128]    = h; g_wl[base + 128]    = l;
        fsplit(v.w, h, l); g_wh[base + 192]    = h; g_wl[base + 192]    = l;
    }
}

// ---------------- bucket fill (launch #2): counts double as cursors --------
__global__ void fill_kernel(const int* __restrict__ ei) {
    int e = blockIdx.x * blockDim.x + threadIdx.x;
    if (e < N_EDGES) {
        int d = ei[N_EDGES + e];
        int p = atomicAdd(&g_counts[d], 1);
        if (p < CAP) g_bkt[(size_t)d * CAP + p] = ei[e];
    }
}

// ---------------- aggregation (launch #3): z = h + sum_nbr h, split at store -
__global__ void agg_kernel(const float* __restrict__ xin, int sel) {
    const float* hin = (sel == 0) ? xin : ((sel == 1) ? g_hA : g_hB);
    int w    = (blockIdx.x * blockDim.x + threadIdx.x) >> 5;
    int lane = threadIdx.x & 31;
    if (w >= NPAD) return;
    float4 acc = make_float4(0.f, 0.f, 0.f, 0.f);
    if (w < N_NODES) {
        const float4* h4 = (const float4*)hin;
        acc = h4[(size_t)w * 32 + lane];
        const int* bkt = g_bkt + (size_t)w * CAP;
        int cnt = g_counts[w];
        int e = (cnt < CAP) ? cnt : CAP;
        int j = 0;
        for (; j + 8 <= e; j += 8) {
            int s0 = bkt[j],     s1 = bkt[j + 1];
            int s2 = bkt[j + 2], s3 = bkt[j + 3];
            int s4 = bkt[j + 4], s5 = bkt[j + 5];
            int s6 = bkt[j + 6], s7 = bkt[j + 7];
            float4 v0 = h4[(size_t)s0 * 32 + lane];
            float4 v1 = h4[(size_t)s1 * 32 + lane];
            float4 v2 = h4[(size_t)s2 * 32 + lane];
            float4 v3 = h4[(size_t)s3 * 32 + lane];
            float4 v4 = h4[(size_t)s4 * 32 + lane];
            float4 v5 = h4[(size_t)s5 * 32 + lane];
            float4 v6 = h4[(size_t)s6 * 32 + lane];
            float4 v7 = h4[(size_t)s7 * 32 + lane];
            acc.x += ((v0.x + v1.x) + (v2.x + v3.x)) + ((v4.x + v5.x) + (v6.x + v7.x));
            acc.y += ((v0.y + v1.y) + (v2.y + v3.y)) + ((v4.y + v5.y) + (v6.y + v7.y));
            acc.z += ((v0.z + v1.z) + (v2.z + v3.z)) + ((v4.z + v5.z) + (v6.z + v7.z));
            acc.w += ((v0.w + v1.w) + (v2.w + v3.w)) + ((v4.w + v5.w) + (v6.w + v7.w));
        }
        for (; j + 4 <= e; j += 4) {
            int s0 = bkt[j],     s1 = bkt[j + 1];
            int s2 = bkt[j + 2], s3 = bkt[j + 3];
            float4 v0 = h4[(size_t)s0 * 32 + lane];
            float4 v1 = h4[(size_t)s1 * 32 + lane];
            float4 v2 = h4[(size_t)s2 * 32 + lane];
            float4 v3 = h4[(size_t)s3 * 32 + lane];
            acc.x += (v0.x + v1.x) + (v2.x + v3.x);
            acc.y += (v0.y + v1.y) + (v2.y + v3.y);
            acc.z += (v0.z + v1.z) + (v2.z + v3.z);
            acc.w += (v0.w + v1.w) + (v2.w + v3.w);
        }
        for (; j < e; j++) {
            int s0 = bkt[j];
            float4 v0 = h4[(size_t)s0 * 32 + lane];
            acc.x += v0.x; acc.y += v0.y; acc.z += v0.z; acc.w += v0.w;
        }
    }
    __half h0, l0, h1, l1, h2, l2, h3, l3;
    fsplit(acc.x, h0, l0); fsplit(acc.y, h1, l1);
    fsplit(acc.z, h2, l2); fsplit(acc.w, h3, l3);
    uint2 hv = make_uint2(pack2(h0, h1), pack2(h2, h3));
    uint2 lv = make_uint2(pack2(l0, l1), pack2(l2, l3));
    ((uint2*)g_zh)[(size_t)w * 32 + lane] = hv;
    ((uint2*)g_zl)[(size_t)w * 32 + lane] = lv;
}

// ---------------- fp16-split tensor-core MLP, M=64 tiles, 3 CTAs/SM ---------
// hout = relu( relu(z @ W1) @ W2 ), 3 products (hh, hl, lh).
// 256 threads = 8 warps as 2x4 grid of 32x32 warp tiles. grid = NPAD/64.
// A (hi/lo, 64x128) resident; B staged per K=64 half.
// SMEM/CTA = 71680 B, regs capped for 3 CTAs/SM (24 warps/SM).

#define ASTR 68    // A row stride in u32 (272 B)
#define BSTR 36    // B row stride in u32 (144 B)
#define OFF_AH 0
#define OFF_AL (64 * ASTR * 4)              // 17408
#define OFF_BH (2 * 64 * ASTR * 4)          // 34816
#define OFF_BL (OFF_BH + 128 * BSTR * 4)    // 53248
#define SMEM_MLP (OFF_BL + 128 * BSTR * 4)  // 71680

__device__ __forceinline__ void mma16(float c[4],
                                      unsigned a0, unsigned a1, unsigned a2, unsigned a3,
                                      unsigned b0, unsigned b1) {
    asm volatile(
        "mma.sync.aligned.m16n8k16.row.col.f32.f16.f16.f32 "
        "{%0,%1,%2,%3}, {%4,%5,%6,%7}, {%8,%9}, {%0,%1,%2,%3};"
        : "+f"(c[0]), "+f"(c[1]), "+f"(c[2]), "+f"(c[3])
        : "r"(a0), "r"(a1), "r"(a2), "r"(a3), "r"(b0), "r"(b1));
}
__device__ __forceinline__ void ldsm4(unsigned& r0, unsigned& r1,
                                      unsigned& r2, unsigned& r3, uint32_t a) {
    asm volatile("ldmatrix.sync.aligned.m8n8.x4.shared.b16 {%0,%1,%2,%3}, [%4];"
                 : "=r"(r0), "=r"(r1), "=r"(r2), "=r"(r3) : "r"(a));
}

// K=64 half-GEMM: c += A(hi+lo)[:, half] @ B(hi+lo)^T dropping lo*lo.
// Warp tile 32x32 (2 mf x 4 nf fragments).
__device__ __forceinline__ void gemm_half(uint32_t sAh, uint32_t sAl,
                                          uint32_t sBh, uint32_t sBl,
                                          float c[2][4][4], int wm, int wn,
                                          int lane, int half) {
    const int lrowA = (lane & 7) | (((lane >> 3) & 1) << 3);
    const int lkA   = (lane >> 4) << 3;                     // halves
    const int lrowB = (lane & 7) | ((lane >> 4) << 3);
    const int lkB   = ((lane >> 3) & 1) << 3;               // halves
#pragma unroll
    for (int ks = 0; ks < 4; ks++) {
        const int k0a = half * 64 + ks * 16;
        const int k0b = ks * 16;
        unsigned ah[2][4], al[2][4];
#pragma unroll
        for (int mf = 0; mf < 2; mf++) {
            uint32_t aoff = (uint32_t)((wm * 32 + mf * 16 + lrowA) * (ASTR * 4)
                                       + (k0a + lkA) * 2);
            ldsm4(ah[mf][0], ah[mf][1], ah[mf][2], ah[mf][3], sAh + aoff);
            ldsm4(al[mf][0], al[mf][1], al[mf][2], al[mf][3], sAl + aoff);
        }
        unsigned bh[4][2], bl[4][2];
#pragma unroll
        for (int np = 0; np < 2; np++) {
            uint32_t boff = (uint32_t)((wn * 32 + np * 16 + lrowB) * (BSTR * 4)
                                       + (k0b + lkB) * 2);
            ldsm4(bh[2 * np][0], bh[2 * np][1], bh[2 * np + 1][0], bh[2 * np + 1][1],
                  sBh + boff);
            ldsm4(bl[2 * np][0], bl[2 * np][1], bl[2 * np + 1][0], bl[2 * np + 1][1],
                  sBl + boff);
        }
#pragma unroll
        for (int mf = 0; mf < 2; mf++)
#pragma unroll
            for (int nf = 0; nf < 4; nf++) {
                mma16(c[mf][nf], ah[mf][0], ah[mf][1], ah[mf][2], ah[mf][3],
                      bh[nf][0], bh[nf][1]);
                mma16(c[mf][nf], ah[mf][0], ah[mf][1], ah[mf][2], ah[mf][3],
                      bl[nf][0], bl[nf][1]);
                mma16(c[mf][nf], al[mf][0], al[mf][1], al[mf][2], al[mf][3],
                      bh[nf][0], bh[nf][1]);
            }
    }
}

__global__ __launch_bounds__(256, 3)
void gin_mlp(int mbase, int outsel) {
    extern __shared__ char smc[];
    const uint32_t sbase = (uint32_t)__cvta_generic_to_shared(smc);
    const uint32_t sAh = sbase + OFF_AH, sAl = sbase + OFF_AL;
    const uint32_t sBh = sbase + OFF_BH, sBl = sbase + OFF_BL;
    unsigned* Ah = (unsigned*)(smc + OFF_AH);
    unsigned* Al = (unsigned*)(smc + OFF_AL);
    float* hout = (outsel == 1) ? g_hA : g_hB;

    const int tid = threadIdx.x;
    const int lane = tid & 31;
    const int warp = tid >> 5;
    const int wm = warp >> 2, wn = warp & 3;
    const int g = lane >> 2, tq = lane & 3;

    // ---- A staging: vector copy of precomputed hi/lo z tile (64 rows) ----
    {
        const uint4* zh = (const uint4*)g_zh + (size_t)blockIdx.x * 1024;
        const uint4* zl = (const uint4*)g_zl + (size_t)blockIdx.x * 1024;
#pragma unroll
        for (int i = 0; i < 4; i++) {
            int u = tid + i * 256;                     // 0..1023
            int row = u >> 4, cc = u & 15;
            *(uint4*)(smc + OFF_AH + row * 272 + cc * 16) = zh[u];
            *(uint4*)(smc + OFF_AL + row * 272 + cc * 16) = zl[u];
        }
    }

    float c[2][4][4];

#pragma unroll 1
    for (int gm = 0; gm < 2; gm++) {
#pragma unroll
        for (int mf = 0; mf < 2; mf++)
#pragma unroll
            for (int nf = 0; nf < 4; nf++)
#pragma unroll
                for (int q = 0; q < 4; q++) c[mf][nf][q] = 0.f;

#pragma unroll
        for (int half = 0; half < 2; half++) {
            // ---- B staging: vector copy of precomputed W hi/lo half ----
            const uint4* wh = (const uint4*)(g_wh +
                (size_t)((mbase + gm) * 2 + half) * 128 * 64);
            const uint4* wl = (const uint4*)(g_wl +
                (size_t)((mbase + gm) * 2 + half) * 128 * 64);
#pragma unroll
            for (int i = 0; i < 4; i++) {
                int u = tid + i * 256;                 // 0..1023
                int row = u >> 3, cc = u & 7;
                *(uint4*)(smc + OFF_BH + row * 144 + cc * 16) = wh[u];
                *(uint4*)(smc + OFF_BL + row * 144 + cc * 16) = wl[u];
            }
            __syncthreads();
            gemm_half(sAh, sAl, sBh, sBl, c, wm, wn, lane, half);
            __syncthreads();
        }

        if (gm == 0) {
            // ---- t = relu(.) split back into Ah/Al (the only in-kernel split) ----
#pragma unroll
            for (int mf = 0; mf < 2; mf++)
#pragma unroll
                for (int nf = 0; nf < 4; nf++) {
                    int r  = wm * 32 + mf * 16 + g;
                    int cu = wn * 16 + nf * 4 + tq;
                    float v0 = fmaxf(c[mf][nf][0], 0.f), v1 = fmaxf(c[mf][nf][1], 0.f);
                    float v2 = fmaxf(c[mf][nf][2], 0.f), v3 = fmaxf(c[mf][nf][3], 0.f);
                    __half h0, l0, h1, l1, h2, l2, h3, l3;
                    fsplit(v0, h0, l0); fsplit(v1, h1, l1);
                    fsplit(v2, h2, l2); fsplit(v3, h3, l3);
                    Ah[r * ASTR + cu]       = pack2(h0, h1);
                    Al[r * ASTR + cu]       = pack2(l0, l1);
                    Ah[(r + 8) * ASTR + cu] = pack2(h2, h3);
                    Al[(r + 8) * ASTR + cu] = pack2(l2, l3);
                }
            __syncthreads();
        }
    }

    // ---- relu -> gmem ----
    const size_t row0 = (size_t)blockIdx.x * 64;
#pragma unroll
    for (int mf = 0; mf < 2; mf++)
#pragma unroll
        for (int nf = 0; nf < 4; nf++) {
            int r  = wm * 32 + mf * 16 + g;
            int cc = wn * 32 + nf * 8 + tq * 2;
            float2 o0, o1;
            o0.x = fmaxf(c[mf][nf][0], 0.f); o0.y = fmaxf(c[mf][nf][1], 0.f);
            o1.x = fmaxf(c[mf][nf][2], 0.f); o1.y = fmaxf(c[mf][nf][3], 0.f);
            *(float2*)&hout[(row0 + r) * D + cc]     = o0;
            *(float2*)&hout[(row0 + r + 8) * D + cc] = o1;
        }
}

// ---------------- pooling: segmented reduction exploiting sorted batch ----------
__global__ __launch_bounds__(128)
void pool_kernel(const int* __restrict__ batch) {
    int f = threadIdx.x;
    int n0 = blockIdx.x * 128;
    float s = 0.f, m = 0.f;
    int cur = -1, cnt = 0;
    for (int i = 0; i < 128; i++) {
        int n = n0 + i;
        if (n >= N_NODES) break;
        int gg = batch[n];
        if (gg != cur) {
            if (cur >= 0) {
                atomicAdd(&g_gsum[cur * D + f], s);
                atomicMax(&g_gmax[cur * D + f], __float_as_uint(m));  // h >= 0
                if (f == 0) atomicAdd(&g_gcnt[cur], cnt);
            }
            cur = gg; s = 0.f; m = 0.f; cnt = 0;
        }
        float v = g_hA[(size_t)n * D + f];
        s += v;
        m = fmaxf(m, v);
        cnt++;
    }
    if (cur >= 0) {
        atomicAdd(&g_gsum[cur * D + f], s);
        atomicMax(&g_gmax[cur * D + f], __float_as_uint(m));
        if (f == 0) atomicAdd(&g_gcnt[cur], cnt);
    }
}

// ---------------- readout: [gmax | gmean | gsum] @ out_w + out_b ----------------
__global__ void readout_kernel(const float* __restrict__ ow,
                               const float* __restrict__ ob,
                               float* __restrict__ out) {
    __shared__ float p[3 * D];
    int g = blockIdx.x;
    int o = threadIdx.x;
    if (o < D) {
        float s = g_gsum[g * D + o];
        float cn = fmaxf((float)g_gcnt[g], 1.f);
        p[o]         = __uint_as_float(g_gmax[g * D + o]);
        p[D + o]     = s / cn;
        p[2 * D + o] = s;
    }
    __syncthreads();
    float acc = ob[o];
#pragma unroll 8
    for (int f = 0; f < 3 * D; f++) acc = fmaf(p[f], ow[f * OUTF + o], acc);
    out[g * OUTF + o] = acc;
}

// ---------------- launch ----------------
extern "C" void kernel_launch(void* const* d_in, const int* in_sizes, int n_in,
                              void* d_out, int out_size) {
    const float* x      = (const float*)d_in[0];
    const int*   ei     = (const int*)  d_in[1];
    const int*   batch  = (const int*)  d_in[2];
    const float* w1_0   = (const float*)d_in[3];
    const float* w2_0   = (const float*)d_in[4];
    const float* gin_w1 = (const float*)d_in[5];   // [2][128][128]
    const float* gin_w2 = (const float*)d_in[6];
    const float* out_w  = (const float*)d_in[7];   // [384][256]
    const float* out_b  = (const float*)d_in[8];
    float* out = (float*)d_out;

    cudaFuncSetAttribute(gin_mlp,
                         cudaFuncAttributeMaxDynamicSharedMemorySize, SMEM_MLP);

    const int AGG_BLOCKS = NPAD / 8;  // 8 warps/block, 1 warp/node

    // launches: zero+wsplit(1), fill(2), agg(3), mlp(4 <- profiled slot), ...
    zero_kernel<<<(N_NODES + 255) / 256, 256>>>(w1_0, w2_0, gin_w1, gin_w2);
    fill_kernel<<<(N_EDGES + 255) / 256, 256>>>(ei);

    // layer 0: x -> hA
    agg_kernel<<<AGG_BLOCKS, 256>>>(x, 0);
    gin_mlp<<<MLP_TILES, 256, SMEM_MLP>>>(0, 1);
    // layer 1: hA -> hB
    agg_kernel<<<AGG_BLOCKS, 256>>>(x, 1);
    gin_mlp<<<MLP_TILES, 256, SMEM_MLP>>>(2, 2);
    // layer 2: hB -> hA
    agg_kernel<<<AGG_BLOCKS, 256>>>(x, 2);
    gin_mlp<<<MLP_TILES, 256, SMEM_MLP>>>(4, 1);

    // pooling + readout
    pool_kernel<<<N_TILES, 128>>>(batch);
    readout_kernel<<<NGRAPH, 256>>>(out_w, out_b, out);
}

// round 14
// speedup vs baseline: 1.0290x; 1.0290x over previous
#include <cuda_runtime.h>
#include <cuda_fp16.h>
#include <cstdint>

// Problem constants (fixed by the dataset)
#define N_NODES 50000
#define NPAD    50048            // 391 * 128
#define N_EDGES 800000
#define D       128
#define NGRAPH  256
#define OUTF    256
#define N_TILES (NPAD / 128)     // 391  (pool tiling)
#define MLP_TILES (NPAD / 64)    // 782  (MLP M=64 tiling)
#define CAP     64               // max in-degree capacity (Poisson(16) tail ~1e-13)

// ---------------- device scratch (no allocations allowed) ----------------
__device__ float    g_hA[(size_t)NPAD * D];
__device__ float    g_hB[(size_t)NPAD * D];
__device__ unsigned g_zh[(size_t)NPAD * 64];   // z hi, packed half2, [node][64 u32]
__device__ unsigned g_zl[(size_t)NPAD * 64];   // z lo
__device__ __half   g_wh[6 * 2 * 128 * 64];    // W hi, [mat][khalf][n][64 halves]
__device__ __half   g_wl[6 * 2 * 128 * 64];    // W lo
__device__ int      g_counts[N_NODES];
__device__ int      g_bkt[(size_t)N_NODES * CAP];
__device__ float    g_gsum[NGRAPH * D];
__device__ unsigned g_gmax[NGRAPH * D];
__device__ int      g_gcnt[NGRAPH];

__device__ __forceinline__ void fsplit(float v, __half& hi, __half& lo) {
    hi = __float2half_rn(v);
    lo = __float2half_rn(v - __half2float(hi));
}
__device__ __forceinline__ unsigned pack2(__half a, __half b) {
    union { __half2 h; unsigned u; } q;
    q.h = __halves2half2(a, b);
    return q.u;
}

// ---------------- init + one-time W split (launch #1) ----------------
__global__ void zero_kernel(const float* __restrict__ w1_0,
                            const float* __restrict__ w2_0,
                            const float* __restrict__ gw1,
                            const float* __restrict__ gw2) {
    int i = blockIdx.x * blockDim.x + threadIdx.x;
    if (i < N_NODES) g_counts[i] = 0;
    if (i < NGRAPH * D) { g_gsum[i] = 0.f; g_gmax[i] = 0u; }
    if (i < NGRAPH) g_gcnt[i] = 0;
    if (i < 6 * 128 * 32) {
        int m = i / (128 * 32);
        int r = i % (128 * 32);
        int k = r >> 5;                  // 0..127
        int n4 = (r & 31) * 4;
        const float* W;
        switch (m) {
            case 0: W = w1_0; break;
            case 1: W = w2_0; break;
            case 2: W = gw1; break;
            case 3: W = gw2; break;
            case 4: W = gw1 + 128 * 128; break;
            default: W = gw2 + 128 * 128; break;
        }
        float4 v = ((const float4*)W)[k * 32 + (r & 31)];
        int kh = k >> 6, kl = k & 63;
        size_t base = ((size_t)(m * 2 + kh) * 128 + n4) * 64 + kl;
        __half h, l;
        fsplit(v.x, h, l); g_wh[base]          = h; g_wl[base]          = l;
        fsplit(v.y, h, l); g_wh[base + 64]     = h; g_wl[base + 64]     = l;
        fsplit(v.z, h, l); g_wh[base + 128]    = h; g_wl[base + 128]    = l;
        fsplit(v.w, h, l); g_wh[base + 192]    = h; g_wl[base + 192]    = l;
    }
}

// ---------------- bucket fill (launch #2): counts double as cursors --------
__global__ void fill_kernel(const int* __restrict__ ei) {
    int e = blockIdx.x * blockDim.x + threadIdx.x;
    if (e < N_EDGES) {
        int d = ei[N_EDGES + e];
        int p = atomicAdd(&g_counts[d], 1);
        if (p < CAP) g_bkt[(size_t)d * CAP + p] = ei[e];
    }
}

// ---------------- aggregation (launch #3): z = h + sum_nbr h, split at store -
__global__ void agg_kernel(const float* __restrict__ xin, int sel) {
    const float* hin = (sel == 0) ? xin : ((sel == 1) ? g_hA : g_hB);
    int w    = (blockIdx.x * blockDim.x + threadIdx.x) >> 5;
    int lane = threadIdx.x & 31;
    if (w >= NPAD) return;
    float4 acc = make_float4(0.f, 0.f, 0.f, 0.f);
    if (w < N_NODES) {
        const float4* h4 = (const float4*)hin;
        acc = h4[(size_t)w * 32 + lane];
        const int* bkt = g_bkt + (size_t)w * CAP;
        int cnt = g_counts[w];
        int e = (cnt < CAP) ? cnt : CAP;
        int j = 0;
        for (; j + 8 <= e; j += 8) {
            int s0 = bkt[j],     s1 = bkt[j + 1];
            int s2 = bkt[j + 2], s3 = bkt[j + 3];
            int s4 = bkt[j + 4], s5 = bkt[j + 5];
            int s6 = bkt[j + 6], s7 = bkt[j + 7];
            float4 v0 = h4[(size_t)s0 * 32 + lane];
            float4 v1 = h4[(size_t)s1 * 32 + lane];
            float4 v2 = h4[(size_t)s2 * 32 + lane];
            float4 v3 = h4[(size_t)s3 * 32 + lane];
            float4 v4 = h4[(size_t)s4 * 32 + lane];
            float4 v5 = h4[(size_t)s5 * 32 + lane];
            float4 v6 = h4[(size_t)s6 * 32 + lane];
            float4 v7 = h4[(size_t)s7 * 32 + lane];
            acc.x += ((v0.x + v1.x) + (v2.x + v3.x)) + ((v4.x + v5.x) + (v6.x + v7.x));
            acc.y += ((v0.y + v1.y) + (v2.y + v3.y)) + ((v4.y + v5.y) + (v6.y + v7.y));
            acc.z += ((v0.z + v1.z) + (v2.z + v3.z)) + ((v4.z + v5.z) + (v6.z + v7.z));
            acc.w += ((v0.w + v1.w) + (v2.w + v3.w)) + ((v4.w + v5.w) + (v6.w + v7.w));
        }
        for (; j + 4 <= e; j += 4) {
            int s0 = bkt[j],     s1 = bkt[j + 1];
            int s2 = bkt[j + 2], s3 = bkt[j + 3];
            float4 v0 = h4[(size_t)s0 * 32 + lane];
            float4 v1 = h4[(size_t)s1 * 32 + lane];
            float4 v2 = h4[(size_t)s2 * 32 + lane];
            float4 v3 = h4[(size_t)s3 * 32 + lane];
            acc.x += (v0.x + v1.x) + (v2.x + v3.x);
            acc.y += (v0.y + v1.y) + (v2.y + v3.y);
            acc.z += (v0.z + v1.z) + (v2.z + v3.z);
            acc.w += (v0.w + v1.w) + (v2.w + v3.w);
        }
        for (; j < e; j++) {
            int s0 = bkt[j];
            float4 v0 = h4[(size_t)s0 * 32 + lane];
            acc.x += v0.x; acc.y += v0.y; acc.z += v0.z; acc.w += v0.w;
        }
    }
    __half h0, l0, h1, l1, h2, l2, h3, l3;
    fsplit(acc.x, h0, l0); fsplit(acc.y, h1, l1);
    fsplit(acc.z, h2, l2); fsplit(acc.w, h3, l3);
    uint2 hv = make_uint2(pack2(h0, h1), pack2(h2, h3));
    uint2 lv = make_uint2(pack2(l0, l1), pack2(l2, l3));
    ((uint2*)g_zh)[(size_t)w * 32 + lane] = hv;
    ((uint2*)g_zl)[(size_t)w * 32 + lane] = lv;
}

// ---------------- fp16-split TC MLP: M=64, cp.async double-buffered B -------
// hout = relu( relu(z @ W1) @ W2 ), 3 products (hh, hl, lh).
// 256 threads = 8 warps as 2x4 grid of 32x32 warp tiles. grid = NPAD/64.
// Stages S0..S3 = {G1H0, G1H1, G2H0, G2H1}; B stage s -> buf s&1, prefetched
// one stage ahead via cp.async groups. SMEM/CTA = 108544 B -> 2 CTAs/SM.

#define ASTR 68    // A row stride in u32 (272 B)
#define OFF_AH 0
#define OFF_AL (64 * ASTR * 4)              // 17408
#define OFF_B0 (2 * 64 * ASTR * 4)          // 34816
#define BHALF  18432                        // 128 rows * 144 B (hi or lo)
#define BSTAGE (2 * BHALF)                  // 36864
#define SMEM_MLP (OFF_B0 + 2 * BSTAGE)      // 108544

#define CP16(dst, src) \
    asm volatile("cp.async.cg.shared.global [%0], [%1], 16;" \
                 :: "r"(dst), "l"(src))
#define CP_COMMIT() asm volatile("cp.async.commit_group;" ::: "memory")
#define CP_WAIT(n)  asm volatile("cp.async.wait_group %0;" :: "n"(n) : "memory")

__device__ __forceinline__ void mma16(float c[4],
                                      unsigned a0, unsigned a1, unsigned a2, unsigned a3,
                                      unsigned b0, unsigned b1) {
    asm volatile(
        "mma.sync.aligned.m16n8k16.row.col.f32.f16.f16.f32 "
        "{%0,%1,%2,%3}, {%4,%5,%6,%7}, {%8,%9}, {%0,%1,%2,%3};"
        : "+f"(c[0]), "+f"(c[1]), "+f"(c[2]), "+f"(c[3])
        : "r"(a0), "r"(a1), "r"(a2), "r"(a3), "r"(b0), "r"(b1));
}
__device__ __forceinline__ void ldsm4(unsigned& r0, unsigned& r1,
                                      unsigned& r2, unsigned& r3, uint32_t a) {
    asm volatile("ldmatrix.sync.aligned.m8n8.x4.shared.b16 {%0,%1,%2,%3}, [%4];"
                 : "=r"(r0), "=r"(r1), "=r"(r2), "=r"(r3) : "r"(a));
}

// async copy of one W stage (hi+lo) into buffer buf
__device__ __forceinline__ void copy_B_async(uint32_t sbase, int buf,
                                             int mat, int kh, int tid) {
    const __half* wh = g_wh + (size_t)(mat * 2 + kh) * 128 * 64;
    const __half* wl = g_wl + (size_t)(mat * 2 + kh) * 128 * 64;
    uint32_t dh = sbase + OFF_B0 + buf * BSTAGE;
    uint32_t dl = dh + BHALF;
#pragma unroll
    for (int i = 0; i < 4; i++) {
        int u = tid + i * 256;                 // 0..1023 (16B units)
        uint32_t off = (u >> 3) * 144 + (u & 7) * 16;
        CP16(dh + off, (const char*)wh + (size_t)u * 16);
        CP16(dl + off, (const char*)wl + (size_t)u * 16);
    }
}

// K=64 half-GEMM: c += A(hi+lo)[:, kh] @ B(hi+lo)^T dropping lo*lo.
__device__ __forceinline__ void gemm_half(uint32_t sAh, uint32_t sAl,
                                          uint32_t sBh, uint32_t sBl,
                                          float c[2][4][4], int wm, int wn,
                                          int lane, int kh) {
    const int lrowA = (lane & 7) | (((lane >> 3) & 1) << 3);
    const int lkA   = (lane >> 4) << 3;                     // halves
    const int lrowB = (lane & 7) | ((lane >> 4) << 3);
    const int lkB   = ((lane >> 3) & 1) << 3;               // halves
#pragma unroll
    for (int ks = 0; ks < 4; ks++) {
        const int k0a = kh * 64 + ks * 16;
        const int k0b = ks * 16;
        unsigned ah[2][4], al[2][4];
#pragma unroll
        for (int mf = 0; mf < 2; mf++) {
            uint32_t aoff = (uint32_t)((wm * 32 + mf * 16 + lrowA) * (ASTR * 4)
                                       + (k0a + lkA) * 2);
            ldsm4(ah[mf][0], ah[mf][1], ah[mf][2], ah[mf][3], sAh + aoff);
            ldsm4(al[mf][0], al[mf][1], al[mf][2], al[mf][3], sAl + aoff);
        }
        unsigned bh[4][2], bl[4][2];
#pragma unroll
        for (int np = 0; np < 2; np++) {
            uint32_t boff = (uint32_t)((wn * 32 + np * 16 + lrowB) * 144
                                       + (k0b + lkB) * 2);
            ldsm4(bh[2 * np][0], bh[2 * np][1], bh[2 * np + 1][0], bh[2 * np + 1][1],
                  sBh + boff);
            ldsm4(bl[2 * np][0], bl[2 * np][1], bl[2 * np + 1][0], bl[2 * np + 1][1],
                  sBl + boff);
        }
#pragma unroll
        for (int mf = 0; mf < 2; mf++)
#pragma unroll
            for (int nf = 0; nf < 4; nf++) {
                mma16(c[mf][nf], ah[mf][0], ah[mf][1], ah[mf][2], ah[mf][3],
                      bh[nf][0], bh[nf][1]);
                mma16(c[mf][nf], ah[mf][0], ah[mf][1], ah[mf][2], ah[mf][3],
                      bl[nf][0], bl[nf][1]);
                mma16(c[mf][nf], al[mf][0], al[mf][1], al[mf][2], al[mf][3],
                      bh[nf][0], bh[nf][1]);
            }
    }
}

__global__ __launch_bounds__(256, 2)
void gin_mlp(int mbase, int outsel) {
    extern __shared__ char smc[];
    const uint32_t sbase = (uint32_t)__cvta_generic_to_shared(smc);
    const uint32_t sAh = sbase + OFF_AH, sAl = sbase + OFF_AL;
    unsigned* Ah = (unsigned*)(smc + OFF_AH);
    unsigned* Al = (unsigned*)(smc + OFF_AL);
    float* hout = (outsel == 1) ? g_hA : g_hB;

    const int tid = threadIdx.x;
    const int lane = tid & 31;
    const int warp = tid >> 5;
    const int wm = warp >> 2, wn = warp & 3;
    const int g = lane >> 2, tq = lane & 3;

    // group0: A (hi/lo z tile, 64 rows) + B stage0 ; group1: B stage1
    {
        const uint4* zh = (const uint4*)g_zh + (size_t)blockIdx.x * 1024;
        const uint4* zl = (const uint4*)g_zl + (size_t)blockIdx.x * 1024;
#pragma unroll
        for (int i = 0; i < 4; i++) {
            int u = tid + i * 256;                     // 0..1023
            uint32_t off = (u >> 4) * 272 + (u & 15) * 16;
            CP16(sAh + off, (const char*)(zh + u));
            CP16(sAl + off, (const char*)(zl + u));
        }
    }
    copy_B_async(sbase, 0, mbase + 0, 0, tid);
    CP_COMMIT();                                   // g0 = A + S0
    copy_B_async(sbase, 1, mbase + 0, 1, tid);
    CP_COMMIT();                                   // g1 = S1

    float c[2][4][4];
#pragma unroll
    for (int mf = 0; mf < 2; mf++)
#pragma unroll
        for (int nf = 0; nf < 4; nf++)
#pragma unroll
            for (int q = 0; q < 4; q++) c[mf][nf][q] = 0.f;

    // ---- S0: GEMM1 half0 (buf0) ----
    CP_WAIT(1);
    __syncthreads();
    gemm_half(sAh, sAl, sbase + OFF_B0, sbase + OFF_B0 + BHALF, c, wm, wn, lane, 0);
    __syncthreads();
    copy_B_async(sbase, 0, mbase + 1, 0, tid);     // g2 = S2 into buf0
    CP_COMMIT();

    // ---- S1: GEMM1 half1 (buf1) ----
    CP_WAIT(1);
    __syncthreads();
    gemm_half(sAh, sAl, sbase + OFF_B0 + BSTAGE, sbase + OFF_B0 + BSTAGE + BHALF,
              c, wm, wn, lane, 1);
    __syncthreads();

    // ---- t = relu(.) split back into Ah/Al ----
#pragma unroll
    for (int mf = 0; mf < 2; mf++)
#pragma unroll
        for (int nf = 0; nf < 4; nf++) {
            int r  = wm * 32 + mf * 16 + g;
            int cu = wn * 16 + nf * 4 + tq;
            float v0 = fmaxf(c[mf][nf][0], 0.f), v1 = fmaxf(c[mf][nf][1], 0.f);
            float v2 = fmaxf(c[mf][nf][2], 0.f), v3 = fmaxf(c[mf][nf][3], 0.f);
            __half h0, l0, h1, l1, h2, l2, h3, l3;
            fsplit(v0, h0, l0); fsplit(v1, h1, l1);
            fsplit(v2, h2, l2); fsplit(v3, h3, l3);
            Ah[r * ASTR + cu]       = pack2(h0, h1);
            Al[r * ASTR + cu]       = pack2(l0, l1);
            Ah[(r + 8) * ASTR + cu] = pack2(h2, h3);
            Al[(r + 8) * ASTR + cu] = pack2(l2, l3);
        }
    copy_B_async(sbase, 1, mbase + 1, 1, tid);     // g3 = S3 into buf1
    CP_COMMIT();

#pragma unroll
    for (int mf = 0; mf < 2; mf++)
#pragma unroll
        for (int nf = 0; nf < 4; nf++)
#pragma unroll
            for (int q = 0; q < 4; q++) c[mf][nf][q] = 0.f;

    // ---- S2: GEMM2 half0 (buf0) ----
    CP_WAIT(1);
    __syncthreads();                                // also fences t-split writes
    gemm_half(sAh, sAl, sbase + OFF_B0, sbase + OFF_B0 + BHALF, c, wm, wn, lane, 0);
    __syncthreads();

    // ---- S3: GEMM2 half1 (buf1) ----
    CP_WAIT(0);
    __syncthreads();
    gemm_half(sAh, sAl, sbase + OFF_B0 + BSTAGE, sbase + OFF_B0 + BSTAGE + BHALF,
              c, wm, wn, lane, 1);

    // ---- relu -> gmem ----
    const size_t row0 = (size_t)blockIdx.x * 64;
#pragma unroll
    for (int mf = 0; mf < 2; mf++)
#pragma unroll
        for (int nf = 0; nf < 4; nf++) {
            int r  = wm * 32 + mf * 16 + g;
            int cc = wn * 32 + nf * 8 + tq * 2;
            float2 o0, o1;
            o0.x = fmaxf(c[mf][nf][0], 0.f); o0.y = fmaxf(c[mf][nf][1], 0.f);
            o1.x = fmaxf(c[mf][nf][2], 0.f); o1.y = fmaxf(c[mf][nf][3], 0.f);
            *(float2*)&hout[(row0 + r) * D + cc]     = o0;
            *(float2*)&hout[(row0 + r + 8) * D + cc] = o1;
        }
}

// ---------------- pooling: segmented reduction exploiting sorted batch ----------
__global__ __launch_bounds__(128)
void pool_kernel(const int* __restrict__ batch) {
    int f = threadIdx.x;
    int n0 = blockIdx.x * 128;
    float s = 0.f, m = 0.f;
    int cur = -1, cnt = 0;
    for (int i = 0; i < 128; i++) {
        int n = n0 + i;
        if (n >= N_NODES) break;
        int gg = batch[n];
        if (gg != cur) {
            if (cur >= 0) {
                atomicAdd(&g_gsum[cur * D + f], s);
                atomicMax(&g_gmax[cur * D + f], __float_as_uint(m));  // h >= 0
                if (f == 0) atomicAdd(&g_gcnt[cur], cnt);
            }
            cur = gg; s = 0.f; m = 0.f; cnt = 0;
        }
        float v = g_hA[(size_t)n * D + f];
        s += v;
        m = fmaxf(m, v);
        cnt++;
    }
    if (cur >= 0) {
        atomicAdd(&g_gsum[cur * D + f], s);
        atomicMax(&g_gmax[cur * D + f], __float_as_uint(m));
        if (f == 0) atomicAdd(&g_gcnt[cur], cnt);
    }
}

// ---------------- readout: [gmax | gmean | gsum] @ out_w + out_b ----------------
__global__ void readout_kernel(const float* __restrict__ ow,
                               const float* __restrict__ ob,
                               float* __restrict__ out) {
    __shared__ float p[3 * D];
    int g = blockIdx.x;
    int o = threadIdx.x;
    if (o < D) {
        float s = g_gsum[g * D + o];
        float cn = fmaxf((float)g_gcnt[g], 1.f);
        p[o]         = __uint_as_float(g_gmax[g * D + o]);
        p[D + o]     = s / cn;
        p[2 * D + o] = s;
    }
    __syncthreads();
    float acc = ob[o];
#pragma unroll 8
    for (int f = 0; f < 3 * D; f++) acc = fmaf(p[f], ow[f * OUTF + o], acc);
    out[g * OUTF + o] = acc;
}

// ---------------- launch ----------------
extern "C" void kernel_launch(void* const* d_in, const int* in_sizes, int n_in,
                              void* d_out, int out_size) {
    const float* x      = (const float*)d_in[0];
    const int*   ei     = (const int*)  d_in[1];
    const int*   batch  = (const int*)  d_in[2];
    const float* w1_0   = (const float*)d_in[3];
    const float* w2_0   = (const float*)d_in[4];
    const float* gin_w1 = (const float*)d_in[5];   // [2][128][128]
    const float* gin_w2 = (const float*)d_in[6];
    const float* out_w  = (const float*)d_in[7];   // [384][256]
    const float* out_b  = (const float*)d_in[8];
    float* out = (float*)d_out;

    cudaFuncSetAttribute(gin_mlp,
                         cudaFuncAttributeMaxDynamicSharedMemorySize, SMEM_MLP);

    const int AGG_BLOCKS = NPAD / 8;  // 8 warps/block, 1 warp/node

    // launches: zero+wsplit(1), fill(2), agg(3), mlp(4 <- profiled slot), ...
    zero_kernel<<<(N_NODES + 255) / 256, 256>>>(w1_0, w2_0, gin_w1, gin_w2);
    fill_kernel<<<(N_EDGES + 255) / 256, 256>>>(ei);

    // layer 0: x -> hA
    agg_kernel<<<AGG_BLOCKS, 256>>>(x, 0);
    gin_mlp<<<MLP_TILES, 256, SMEM_MLP>>>(0, 1);
    // layer 1: hA -> hB
    agg_kernel<<<AGG_BLOCKS, 256>>>(x, 1);
    gin_mlp<<<MLP_TILES, 256, SMEM_MLP>>>(2, 2);
    // layer 2: hB -> hA
    agg_kernel<<<AGG_BLOCKS, 256>>>(x, 2);
    gin_mlp<<<MLP_TILES, 256, SMEM_MLP>>>(4, 1);

    // pooling + readout
    pool_kernel<<<N_TILES, 128>>>(batch);
    readout_kernel<<<NGRAPH, 256>>>(out_w, out_b, out);
}